// round 15
// baseline (speedup 1.0000x reference)
#include <cuda_runtime.h>
#include <cstddef>

// NNUE evaluator: single fused kernel, direct fp32 gather (L2-only loads),
// w1 read directly as float4 rows (no transpose pass), streaming output stores.
// 2 blocks/SM.
// d_in: 0 white_idx [B,32] (int32/int64 runtime detected)  1 black_idx
//       2 w_ft [45056,512] f32  3 b_ft[512]  4 w1[1024,32] 5 b1[32]
//       6 w2[32,32] 7 b2[32] 8 w3[32,1] 9 b3[1]
// d_out: features [B,1024] f32 followed by values [B] f32.

#define F_DIM    45056
#define NC4      128          // float4 per 512-wide perspective row
#define NFEAT    1024
#define NACT     32
#define H1       32
#define PB       16
#define PH       8
#define X1S      33
#define NTHR     256

// smem: feat PB*1024 + w2s 1024 + x1s PB*33 + biases 96 + idxs PB*64
#define SMEM_FLOATS (PB*NFEAT + 1024 + PB*X1S + 96 + PB*64)
#define SMEM_BYTES  (SMEM_FLOATS * 4)

__global__ __launch_bounds__(NTHR, 2)
void nnue_fused_kernel(const void* __restrict__ widx_raw,
                       const void* __restrict__ bidx_raw,
                       const float* __restrict__ w_ft,
                       const float* __restrict__ b_ft,
                       const float* __restrict__ w1,
                       const float* __restrict__ b1,
                       const float* __restrict__ w2,
                       const float* __restrict__ b2,
                       const float* __restrict__ w3,
                       const float* __restrict__ b3,
                       float* __restrict__ out_feat,
                       float* __restrict__ out_val,
                       int Bn)
{
    extern __shared__ float smem[];
    float* feat = smem;                         // PB*1024
    float* w2s  = feat + PB*NFEAT;              // 1024
    float* x1s  = w2s + 1024;                   // PB*33
    float* b1s  = x1s + PB*X1S;                 // 32
    float* b2s  = b1s + 32;                     // 32
    float* w3s  = b2s + 32;                     // 32
    int*   idxs = (int*)(w3s + 32);             // PB*64

    const int tid  = threadIdx.x;
    const int lane = tid & 31;
    const int wid  = tid >> 5;

    // ---- one-time staging ----
    for (int e = tid; e < H1 * H1; e += NTHR) w2s[e] = w2[e];
    if (tid < 32) {
        b1s[tid] = b1[tid];
        b2s[tid] = b2[tid];
        w3s[tid] = w3[tid];
    }

    const int is64 = (__ldg((const int*)widx_raw + 1) == 0) ? 1 : 0;
    const float b3v = __ldg(b3);

    const int side = tid >> 7;       // perspective
    const int c    = tid & 127;      // float4 column within perspective
    const float4* __restrict__ wft4 = (const float4*)w_ft;
    const float4 bias = ((const float4*)b_ft)[c];

    // contiguous position range per block
    const int grid = gridDim.x;
    const int base = Bn / grid, rem = Bn % grid;
    const int bid  = blockIdx.x;
    int start, count;
    if (bid < rem) { count = base + 1; start = bid * count; }
    else           { count = base;     start = rem * (base + 1) + (bid - rem) * base; }

    __syncthreads();

    for (int off = 0; off < count; off += PB) {
        const int pos0 = start + off;
        const int npos = (count - off < PB) ? (count - off) : PB;

        // ---- index load (premultiplied by NC4) ----
        const int nIdx = npos * 64;
        for (int e = tid; e < nIdx; e += NTHR) {
            const int p = e >> 6, t = e & 63;
            const void* src = (t < 32) ? widx_raw : bidx_raw;
            const long long g = (long long)(pos0 + p) * NACT + (t & 31);
            int r;
            if (is64) r = (int)((const long long*)src)[g];
            else      r = ((const int*)src)[g];
            idxs[e] = r * NC4;
        }
        __syncthreads();

        // ---- gather: 2 positions interleaved, 8 LDG.128.CG in flight ----
        for (int p0 = 0; p0 < npos; p0 += 2) {
            const bool has2 = (p0 + 1 < npos);
            const int* __restrict__ i0 = idxs + p0 * 64 + side * NACT;
            const int* __restrict__ i1 = idxs + (has2 ? p0 + 1 : p0) * 64 + side * NACT;
            float4 a0 = bias, a1 = bias;
            #pragma unroll
            for (int a = 0; a < NACT; a += 4) {
                float4 v0[4], v1[4];
                #pragma unroll
                for (int u = 0; u < 4; u++) v0[u] = __ldcg(wft4 + i0[a + u] + c);
                #pragma unroll
                for (int u = 0; u < 4; u++) v1[u] = __ldcg(wft4 + i1[a + u] + c);
                #pragma unroll
                for (int u = 0; u < 4; u++) {
                    a0.x += v0[u].x; a0.y += v0[u].y; a0.z += v0[u].z; a0.w += v0[u].w;
                    a1.x += v1[u].x; a1.y += v1[u].y; a1.z += v1[u].z; a1.w += v1[u].w;
                }
            }
            a0.x = fmaxf(a0.x, 0.f); a0.y = fmaxf(a0.y, 0.f);
            a0.z = fmaxf(a0.z, 0.f); a0.w = fmaxf(a0.w, 0.f);
            ((float4*)feat)[p0 * 256 + tid] = a0;
            __stcs((float4*)(out_feat + (size_t)(pos0 + p0) * NFEAT) + tid, a0);
            if (has2) {
                a1.x = fmaxf(a1.x, 0.f); a1.y = fmaxf(a1.y, 0.f);
                a1.z = fmaxf(a1.z, 0.f); a1.w = fmaxf(a1.w, 0.f);
                ((float4*)feat)[(p0 + 1) * 256 + tid] = a1;
                __stcs((float4*)(out_feat + (size_t)(pos0 + p0 + 1) * NFEAT) + tid, a1);
            }
        }
        __syncthreads();

        // ---- layer 1: warp w owns outputs 4w..4w+3; passes of PH positions.
        //      w1[i][j0..j0+3] is contiguous -> one float4 load per (i-chunk,k),
        //      L1-resident (128 KB, protected from eviction by the .cg gather). ----
        {
            const int j0 = wid * 4;
            const float4* __restrict__ w1r = (const float4*)(w1 + j0);   // stride 8 float4 per i

            for (int pbase = 0; pbase < npos; pbase += PH) {
                float acc0[PH], acc1[PH], acc2[PH], acc3[PH];
                #pragma unroll
                for (int pp = 0; pp < PH; pp++) { acc0[pp]=0.f; acc1[pp]=0.f; acc2[pp]=0.f; acc3[pp]=0.f; }

                #pragma unroll
                for (int kk = 0; kk < 8; kk++) {        // i-chunks of 128
                    float4 wr[4];
                    #pragma unroll
                    for (int k = 0; k < 4; k++) {
                        const int i = lane + 32 * (4 * kk + k);
                        wr[k] = __ldg(w1r + (size_t)i * 8);   // w1[i][j0..j0+3]
                    }
                    #pragma unroll
                    for (int pp = 0; pp < PH; pp++) {
                        const int p = pbase + pp;
                        if (p < npos) {
                            #pragma unroll
                            for (int k = 0; k < 4; k++) {
                                const float f = feat[p * NFEAT + lane + 32 * (4 * kk + k)];
                                acc0[pp] = fmaf(f, wr[k].x, acc0[pp]);
                                acc1[pp] = fmaf(f, wr[k].y, acc1[pp]);
                                acc2[pp] = fmaf(f, wr[k].z, acc2[pp]);
                                acc3[pp] = fmaf(f, wr[k].w, acc3[pp]);
                            }
                        }
                    }
                }
                #pragma unroll
                for (int pp = 0; pp < PH; pp++) {
                    const int p = pbase + pp;
                    if (p < npos) {
                        float s0 = acc0[pp], s1 = acc1[pp], s2 = acc2[pp], s3 = acc3[pp];
                        #pragma unroll
                        for (int o = 16; o; o >>= 1) {
                            s0 += __shfl_xor_sync(0xffffffffu, s0, o);
                            s1 += __shfl_xor_sync(0xffffffffu, s1, o);
                            s2 += __shfl_xor_sync(0xffffffffu, s2, o);
                            s3 += __shfl_xor_sync(0xffffffffu, s3, o);
                        }
                        if (lane == 0) {
                            x1s[p * X1S + j0 + 0] = fmaxf(s0 + b1s[j0 + 0], 0.f);
                            x1s[p * X1S + j0 + 1] = fmaxf(s1 + b1s[j0 + 1], 0.f);
                            x1s[p * X1S + j0 + 2] = fmaxf(s2 + b1s[j0 + 2], 0.f);
                            x1s[p * X1S + j0 + 3] = fmaxf(s3 + b1s[j0 + 3], 0.f);
                        }
                    }
                }
            }
        }
        __syncthreads();

        // ---- layers 2+3: one warp per position ----
        for (int p = wid; p < npos; p += 8) {
            float s = b2s[lane];
            #pragma unroll
            for (int i = 0; i < H1; i++)
                s = fmaf(x1s[p * X1S + i], w2s[i * H1 + lane], s);
            s = fmaxf(s, 0.f);
            float v = s * w3s[lane];
            #pragma unroll
            for (int o = 16; o; o >>= 1)
                v += __shfl_xor_sync(0xffffffffu, v, o);
            if (lane == 0)
                __stcs(out_val + pos0 + p, (v + b3v) * 100.0f);
        }
        __syncthreads();
    }
}

extern "C" void kernel_launch(void* const* d_in, const int* in_sizes, int n_in,
                              void* d_out, int out_size)
{
    (void)n_in; (void)out_size;
    const void*  widx = d_in[0];
    const void*  bidx = d_in[1];
    const float* w_ft = (const float*)d_in[2];
    const float* b_ft = (const float*)d_in[3];
    const float* w1   = (const float*)d_in[4];
    const float* b1   = (const float*)d_in[5];
    const float* w2   = (const float*)d_in[6];
    const float* b2   = (const float*)d_in[7];
    const float* w3   = (const float*)d_in[8];
    const float* b3   = (const float*)d_in[9];

    const int Bn = in_sizes[0] / NACT;

    float* out_feat = (float*)d_out;
    float* out_val  = out_feat + (size_t)Bn * NFEAT;

    cudaFuncSetAttribute(nnue_fused_kernel,
                         cudaFuncAttributeMaxDynamicSharedMemorySize,
                         SMEM_BYTES);

    int dev = 0, nsm = 148;
    cudaGetDevice(&dev);
    cudaDeviceGetAttribute(&nsm, cudaDevAttrMultiProcessorCount, dev);
    if (nsm <= 0) nsm = 148;
    int grid = nsm * 2;
    if (grid > Bn) grid = Bn;

    nnue_fused_kernel<<<grid, NTHR, SMEM_BYTES>>>(
        widx, bidx, w_ft, b_ft, w1, b1, w2, b2, w3, b3,
        out_feat, out_val, Bn);
}

// round 17
// speedup vs baseline: 1.1929x; 1.1929x over previous
#include <cuda_runtime.h>
#include <cstddef>

// NNUE evaluator: direct fp32 gather (L2-only loads, 16 in flight), w1 in
// transposed global scratch (L1-resident), streaming output stores. 2 blocks/SM.
// d_in: 0 white_idx [B,32] (int32/int64 runtime detected)  1 black_idx
//       2 w_ft [45056,512] f32  3 b_ft[512]  4 w1[1024,32] 5 b1[32]
//       6 w2[32,32] 7 b2[32] 8 w3[32,1] 9 b3[1]
// d_out: features [B,1024] f32 followed by values [B] f32.

#define F_DIM    45056
#define NC4      128          // float4 per 512-wide perspective row
#define NFEAT    1024
#define NACT     32
#define H1       32
#define PB       16
#define PH       8
#define X1S      33
#define NTHR     256

// scratch: transposed w1 [32][1024]
__device__ __align__(16) float g_w1t[H1 * NFEAT];

// smem: feat PB*1024 + w2s 1024 + x1s PB*33 + biases 96 + idxs PB*64
#define SMEM_FLOATS (PB*NFEAT + 1024 + PB*X1S + 96 + PB*64)
#define SMEM_BYTES  (SMEM_FLOATS * 4)

// ---- tiny prep kernel: transpose w1 [1024,32] -> g_w1t [32][1024] ----
__global__ void w1_transpose_kernel(const float* __restrict__ w1)
{
    const int e = blockIdx.x * blockDim.x + threadIdx.x;
    if (e < NFEAT * H1)
        g_w1t[(e & 31) * NFEAT + (e >> 5)] = w1[e];
}

__global__ __launch_bounds__(NTHR, 2)
void nnue_fused_kernel(const void* __restrict__ widx_raw,
                       const void* __restrict__ bidx_raw,
                       const float* __restrict__ w_ft,
                       const float* __restrict__ b_ft,
                       const float* __restrict__ b1,
                       const float* __restrict__ w2,
                       const float* __restrict__ b2,
                       const float* __restrict__ w3,
                       const float* __restrict__ b3,
                       float* __restrict__ out_feat,
                       float* __restrict__ out_val,
                       int Bn)
{
    extern __shared__ float smem[];
    float* feat = smem;                         // PB*1024
    float* w2s  = feat + PB*NFEAT;              // 1024
    float* x1s  = w2s + 1024;                   // PB*33
    float* b1s  = x1s + PB*X1S;                 // 32
    float* b2s  = b1s + 32;                     // 32
    float* w3s  = b2s + 32;                     // 32
    int*   idxs = (int*)(w3s + 32);             // PB*64

    const int tid  = threadIdx.x;
    const int lane = tid & 31;
    const int wid  = tid >> 5;

    // ---- one-time staging ----
    for (int e = tid; e < H1 * H1; e += NTHR) w2s[e] = w2[e];
    if (tid < 32) {
        b1s[tid] = b1[tid];
        b2s[tid] = b2[tid];
        w3s[tid] = w3[tid];
    }

    const int is64 = (__ldg((const int*)widx_raw + 1) == 0) ? 1 : 0;
    const float b3v = __ldg(b3);

    const int side = tid >> 7;       // perspective
    const int c    = tid & 127;      // float4 column within perspective
    const float4* __restrict__ wft4 = (const float4*)w_ft;
    const float4 bias = ((const float4*)b_ft)[c];

    // contiguous position range per block
    const int grid = gridDim.x;
    const int base = Bn / grid, rem = Bn % grid;
    const int bid  = blockIdx.x;
    int start, count;
    if (bid < rem) { count = base + 1; start = bid * count; }
    else           { count = base;     start = rem * (base + 1) + (bid - rem) * base; }

    __syncthreads();

    for (int off = 0; off < count; off += PB) {
        const int pos0 = start + off;
        const int npos = (count - off < PB) ? (count - off) : PB;

        // ---- index load (premultiplied by NC4) ----
        const int nIdx = npos * 64;
        for (int e = tid; e < nIdx; e += NTHR) {
            const int p = e >> 6, t = e & 63;
            const void* src = (t < 32) ? widx_raw : bidx_raw;
            const long long g = (long long)(pos0 + p) * NACT + (t & 31);
            int r;
            if (is64) r = (int)((const long long*)src)[g];
            else      r = ((const int*)src)[g];
            idxs[e] = r * NC4;
        }
        __syncthreads();

        // ---- gather: 2 positions interleaved, 16 LDG.128.CG in flight ----
        for (int p0 = 0; p0 < npos; p0 += 2) {
            const bool has2 = (p0 + 1 < npos);
            const int* __restrict__ i0 = idxs + p0 * 64 + side * NACT;
            const int* __restrict__ i1 = idxs + (has2 ? p0 + 1 : p0) * 64 + side * NACT;
            float4 a0 = bias, a1 = bias;
            #pragma unroll
            for (int a = 0; a < NACT; a += 8) {
                float4 v0[8], v1[8];
                #pragma unroll
                for (int u = 0; u < 8; u++) v0[u] = __ldcg(wft4 + i0[a + u] + c);
                #pragma unroll
                for (int u = 0; u < 8; u++) v1[u] = __ldcg(wft4 + i1[a + u] + c);
                #pragma unroll
                for (int u = 0; u < 8; u++) {
                    a0.x += v0[u].x; a0.y += v0[u].y; a0.z += v0[u].z; a0.w += v0[u].w;
                    a1.x += v1[u].x; a1.y += v1[u].y; a1.z += v1[u].z; a1.w += v1[u].w;
                }
            }
            a0.x = fmaxf(a0.x, 0.f); a0.y = fmaxf(a0.y, 0.f);
            a0.z = fmaxf(a0.z, 0.f); a0.w = fmaxf(a0.w, 0.f);
            ((float4*)feat)[p0 * 256 + tid] = a0;
            __stcs((float4*)(out_feat + (size_t)(pos0 + p0) * NFEAT) + tid, a0);
            if (has2) {
                a1.x = fmaxf(a1.x, 0.f); a1.y = fmaxf(a1.y, 0.f);
                a1.z = fmaxf(a1.z, 0.f); a1.w = fmaxf(a1.w, 0.f);
                ((float4*)feat)[(p0 + 1) * 256 + tid] = a1;
                __stcs((float4*)(out_feat + (size_t)(pos0 + p0 + 1) * NFEAT) + tid, a1);
            }
        }
        __syncthreads();

        // ---- layer 1: warp w owns outputs 4w..4w+3; passes of PH positions.
        //      w1T rows from global scratch (coalesced, L1-resident). ----
        {
            const int j0 = wid * 4;
            const float* __restrict__ r0 = g_w1t + (j0 + 0) * NFEAT;
            const float* __restrict__ r1 = g_w1t + (j0 + 1) * NFEAT;
            const float* __restrict__ r2 = g_w1t + (j0 + 2) * NFEAT;
            const float* __restrict__ r3 = g_w1t + (j0 + 3) * NFEAT;

            for (int pbase = 0; pbase < npos; pbase += PH) {
                float acc0[PH], acc1[PH], acc2[PH], acc3[PH];
                #pragma unroll
                for (int pp = 0; pp < PH; pp++) { acc0[pp]=0.f; acc1[pp]=0.f; acc2[pp]=0.f; acc3[pp]=0.f; }

                #pragma unroll
                for (int kk = 0; kk < 8; kk++) {        // i-chunks of 128
                    float wr0[4], wr1[4], wr2[4], wr3[4];
                    #pragma unroll
                    for (int k = 0; k < 4; k++) {
                        const int i = lane + 32 * (4 * kk + k);
                        wr0[k] = __ldg(r0 + i);
                        wr1[k] = __ldg(r1 + i);
                        wr2[k] = __ldg(r2 + i);
                        wr3[k] = __ldg(r3 + i);
                    }
                    #pragma unroll
                    for (int pp = 0; pp < PH; pp++) {
                        const int p = pbase + pp;
                        if (p < npos) {
                            #pragma unroll
                            for (int k = 0; k < 4; k++) {
                                const float f = feat[p * NFEAT + lane + 32 * (4 * kk + k)];
                                acc0[pp] = fmaf(f, wr0[k], acc0[pp]);
                                acc1[pp] = fmaf(f, wr1[k], acc1[pp]);
                                acc2[pp] = fmaf(f, wr2[k], acc2[pp]);
                                acc3[pp] = fmaf(f, wr3[k], acc3[pp]);
                            }
                        }
                    }
                }
                #pragma unroll
                for (int pp = 0; pp < PH; pp++) {
                    const int p = pbase + pp;
                    if (p < npos) {
                        float s0 = acc0[pp], s1 = acc1[pp], s2 = acc2[pp], s3 = acc3[pp];
                        #pragma unroll
                        for (int o = 16; o; o >>= 1) {
                            s0 += __shfl_xor_sync(0xffffffffu, s0, o);
                            s1 += __shfl_xor_sync(0xffffffffu, s1, o);
                            s2 += __shfl_xor_sync(0xffffffffu, s2, o);
                            s3 += __shfl_xor_sync(0xffffffffu, s3, o);
                        }
                        if (lane == 0) {
                            x1s[p * X1S + j0 + 0] = fmaxf(s0 + b1s[j0 + 0], 0.f);
                            x1s[p * X1S + j0 + 1] = fmaxf(s1 + b1s[j0 + 1], 0.f);
                            x1s[p * X1S + j0 + 2] = fmaxf(s2 + b1s[j0 + 2], 0.f);
                            x1s[p * X1S + j0 + 3] = fmaxf(s3 + b1s[j0 + 3], 0.f);
                        }
                    }
                }
            }
        }
        __syncthreads();

        // ---- layers 2+3: one warp per position ----
        for (int p = wid; p < npos; p += 8) {
            float s = b2s[lane];
            #pragma unroll
            for (int i = 0; i < H1; i++)
                s = fmaf(x1s[p * X1S + i], w2s[i * H1 + lane], s);
            s = fmaxf(s, 0.f);
            float v = s * w3s[lane];
            #pragma unroll
            for (int o = 16; o; o >>= 1)
                v += __shfl_xor_sync(0xffffffffu, v, o);
            if (lane == 0)
                __stcs(out_val + pos0 + p, (v + b3v) * 100.0f);
        }
        __syncthreads();
    }
}

extern "C" void kernel_launch(void* const* d_in, const int* in_sizes, int n_in,
                              void* d_out, int out_size)
{
    (void)n_in; (void)out_size;
    const void*  widx = d_in[0];
    const void*  bidx = d_in[1];
    const float* w_ft = (const float*)d_in[2];
    const float* b_ft = (const float*)d_in[3];
    const float* w1   = (const float*)d_in[4];
    const float* b1   = (const float*)d_in[5];
    const float* w2   = (const float*)d_in[6];
    const float* b2   = (const float*)d_in[7];
    const float* w3   = (const float*)d_in[8];
    const float* b3   = (const float*)d_in[9];

    const int Bn = in_sizes[0] / NACT;

    float* out_feat = (float*)d_out;
    float* out_val  = out_feat + (size_t)Bn * NFEAT;

    cudaFuncSetAttribute(nnue_fused_kernel,
                         cudaFuncAttributeMaxDynamicSharedMemorySize,
                         SMEM_BYTES);

    int dev = 0, nsm = 148;
    cudaGetDevice(&dev);
    cudaDeviceGetAttribute(&nsm, cudaDevAttrMultiProcessorCount, dev);
    if (nsm <= 0) nsm = 148;
    int grid = nsm * 2;
    if (grid > Bn) grid = Bn;

    w1_transpose_kernel<<<(NFEAT * H1 + 255) / 256, 256>>>(w1);

    nnue_fused_kernel<<<grid, NTHR, SMEM_BYTES>>>(
        widx, bidx, w_ft, b_ft, b1, w2, b2, w3, b3,
        out_feat, out_val, Bn);
}